// round 13
// baseline (speedup 1.0000x reference)
#include <cuda_runtime.h>
#include <cuda_bf16.h>
#include <cstdint>

#define NN   100000
#define NNP  100096          // 782 * 128 (row-padded for GEMM tiles)
#define EE   600000
#define DD   128
#define HH   4
#define FF   32
#define NB4  (NN*4)
#define BKT  64              // bucket slots per node (P(deg>64) ~ 1e-40)

typedef unsigned long long ull;

// ---------------- scratch: device symbols, used ONLY inside device code ----
__device__ __align__(256) uint32_t g_xh[NNP*64];   // leaky(x) bf16-hi pairs (64 words/row)
__device__ __align__(256) uint32_t g_xl[NNP*64];   // leaky(x) bf16-lo pairs
__device__ __align__(256) float    g_h[NNP*DD];    // fc output of current layer
__device__ __align__(256) float    g_el[NB4];
__device__ __align__(256) float    g_er[NB4];
__device__ __align__(256) int      g_deg[NN];      // WITHOUT self loop
__device__ __align__(256) int      g_csrc[NN*BKT];
__device__ __align__(256) uint4    g_wfrag[2*4096]; // frag-layout W (2 layers)
__device__ __align__(256) float    g_c[DD];
__device__ __align__(256) float    g_d[DD];
__device__ float g_cl[HH], g_dl[HH], g_cr[HH], g_dr[HH];

__device__ __forceinline__ float lrelu02(float x){ return (x >= 0.f) ? x : 0.2f*x; }
__device__ __forceinline__ float lrelu001(float x){ return (x >= 0.f) ? x : 0.01f*x; }

// bf16 hi/lo split of two floats -> packed bf16x2 words
__device__ __forceinline__ uint32_t bfsplit2(float x0, float x1, uint32_t& lo){
    __nv_bfloat16 h0 = __float2bfloat16(x0);
    __nv_bfloat16 h1 = __float2bfloat16(x1);
    float r0 = x0 - __bfloat162float(h0);
    float r1 = x1 - __bfloat162float(h1);
    __nv_bfloat16 g0 = __float2bfloat16(r0);
    __nv_bfloat16 g1 = __float2bfloat16(r1);
    lo = (uint32_t)__bfloat16_as_ushort(g0) | ((uint32_t)__bfloat16_as_ushort(g1) << 16);
    return (uint32_t)__bfloat16_as_ushort(h0) | ((uint32_t)__bfloat16_as_ushort(h1) << 16);
}

// warp-level bf16 MMA (baseline sm_80+ PTX; compiles at compute_103)
#define MMA_BF16(d, a, b0, b1) \
    asm volatile("mma.sync.aligned.m16n8k16.row.col.f32.bf16.bf16.f32 " \
        "{%0,%1,%2,%3}, {%4,%5,%6,%7}, {%8,%9}, {%0,%1,%2,%3};" \
        : "+f"((d)[0]), "+f"((d)[1]), "+f"((d)[2]), "+f"((d)[3]) \
        : "r"((a)[0]), "r"((a)[1]), "r"((a)[2]), "r"((a)[3]), "r"(b0), "r"(b1))

// ---------------- init: zero deg + (block 0) layer-0 rank-1 prep ------------
__global__ void k_init(const float* __restrict__ linW, const float* __restrict__ linb,
                       const float* __restrict__ W0,
                       const float* __restrict__ al0, const float* __restrict__ ar0){
    int i = blockIdx.x*blockDim.x + threadIdx.x;
    if (i < NN) g_deg[i] = 0;
    if (blockIdx.x == 0 && threadIdx.x < 128){
        int j = threadIdx.x;
        float c = 0.f, d = 0.f;
        const float* wr = W0 + j*DD;
        #pragma unroll 8
        for (int k = 0; k < DD; k++){
            float w = wr[k];
            c += linW[k]*w;
            d += linb[k]*w;
        }
        g_c[j] = c; g_d[j] = d;
        float alv = al0[j], arv = ar0[j];
        float cl = c*alv, dl = d*alv, cr = c*arv, dr = d*arv;
        #pragma unroll
        for (int o = 16; o; o >>= 1){
            cl += __shfl_down_sync(0xffffffffu, cl, o);
            dl += __shfl_down_sync(0xffffffffu, dl, o);
            cr += __shfl_down_sync(0xffffffffu, cr, o);
            dr += __shfl_down_sync(0xffffffffu, dr, o);
        }
        int lane = j & 31, hd = j >> 5;
        if (lane == 0){ g_cl[hd]=cl; g_dl[hd]=dl; g_cr[hd]=cr; g_dr[hd]=dr; }
    }
}

// ---------------- bucket fill: hist + fill fused (no scan needed) -----------
__global__ void k_fillbucket(const int* __restrict__ src, const int* __restrict__ dst){
    int i = blockIdx.x*blockDim.x + threadIdx.x;
    if (i < EE){
        int d = dst[i];
        int pos = atomicAdd(&g_deg[d], 1);
        if (pos < BKT) g_csrc[d*BKT + pos] = src[i];
    }
}

// ---------------- W pre-conversion to fragment layout (both layers) ---------
// g_wfrag[l][(ks*16+nt)*32 + lane] = {bh0, bh1, bl0, bl1}
__global__ void k_wconv(const float* __restrict__ fcW){
    int t = blockIdx.x*blockDim.x + threadIdx.x;   // 0..8191
    if (t >= 2*4096) return;
    int l    = t >> 12;
    int r    = t & 4095;
    int lane = r & 31;
    int nt   = (r >> 5) & 15;
    int ks   = r >> 9;
    int qr = lane >> 2, qc = lane & 3;
    int n   = nt*8 + qr;
    int kp0 = ks*8 + qc;                            // kpair index (2 floats)
    const float* W = fcW + (size_t)(l+1)*DD*DD;
    float2 w0 = *(const float2*)&W[n*DD + kp0*2];
    float2 w1 = *(const float2*)&W[n*DD + (kp0+4)*2];
    uint32_t lo0, lo1;
    uint32_t hi0 = bfsplit2(w0.x, w0.y, lo0);
    uint32_t hi1 = bfsplit2(w1.x, w1.y, lo1);
    g_wfrag[l*4096 + r] = make_uint4(hi0, hi1, lo0, lo1);
}

// ---------------- HMMA split-bf16 GEMM + fused el/er (layers 1,2) ----------
// g_h = xsplit @ W^T ; h = Ahi*Whi + Ahi*Wlo + Alo*Whi (fp32 accum)
// A from g_xh/g_xl (64 uint32/row, pre-split by producer); B via g_wfrag (L1)
#define WP 68
#define SM_BYTES (2*128*WP*4)     // 69632: Xhi + Xlo (stage aliases after MMA)

__global__ void __launch_bounds__(256)
k_hgemm(int layer, const float* __restrict__ al, const float* __restrict__ ar){
    extern __shared__ __align__(16) uint32_t sm[];
    uint32_t* Xhi = sm;
    uint32_t* Xlo = sm + 128*WP;
    float*    stagef = (float*)sm;                // reuse after MMA (post-sync)

    int tid  = threadIdx.x;
    int w    = tid >> 5;
    int lane = tid & 31;
    int qr   = lane >> 2, qc = lane & 3;
    int row0 = blockIdx.x * 128;
    int rw   = w * 16;
    const uint4* wf = g_wfrag + layer*4096;

    // ---- stage pre-split x tile (raw copy, coalesced): 16 uint4/row ----
    {
        const uint4* xh4 = (const uint4*)&g_xh[(size_t)row0*64];
        const uint4* xl4 = (const uint4*)&g_xl[(size_t)row0*64];
        #pragma unroll
        for (int j = 0; j < 8; j++){
            int idx = j*256 + tid;                // uint4 index (2048 total)
            int r = idx >> 4, c4 = idx & 15;
            uint4 vh = xh4[idx];
            uint4 vl = xl4[idx];
            *(uint4*)&Xhi[r*WP + c4*4] = vh;
            *(uint4*)&Xlo[r*WP + c4*4] = vl;
        }
    }
    __syncthreads();

    // ---- compute: warp w owns rows rw..rw+15, all 128 cols ----
    float acc[16][4];
    #pragma unroll
    for (int nt = 0; nt < 16; nt++)
        #pragma unroll
        for (int i = 0; i < 4; i++) acc[nt][i] = 0.f;

    #pragma unroll
    for (int ks = 0; ks < 8; ks++){
        int abase = (rw + qr)*WP + ks*8 + qc;
        uint32_t ahi[4], alo[4];
        ahi[0] = Xhi[abase];          ahi[1] = Xhi[abase + 8*WP];
        ahi[2] = Xhi[abase + 4];      ahi[3] = Xhi[abase + 8*WP + 4];
        alo[0] = Xlo[abase];          alo[1] = Xlo[abase + 8*WP];
        alo[2] = Xlo[abase + 4];      alo[3] = Xlo[abase + 8*WP + 4];
        #pragma unroll 4
        for (int nt = 0; nt < 16; nt++){
            uint4 b = wf[(ks*16 + nt)*32 + lane]; // L1-resident broadcast table
            MMA_BF16(acc[nt], ahi, b.x, b.y);     // Ahi*Whi
            MMA_BF16(acc[nt], ahi, b.z, b.w);     // Ahi*Wlo
            MMA_BF16(acc[nt], alo, b.x, b.y);     // Alo*Whi
        }
    }
    __syncthreads();                              // all warps done reading X smem

    // ---- epilogue: stage h + el/er from fragments ----
    float sl0[4], sr0[4], sl1[4], sr1[4];
    #pragma unroll
    for (int h = 0; h < 4; h++){ sl0[h]=0.f; sr0[h]=0.f; sl1[h]=0.f; sr1[h]=0.f; }
    #pragma unroll
    for (int nt = 0; nt < 16; nt++){
        int col = nt*8 + qc*2;
        float c0 = acc[nt][0], c1 = acc[nt][1], c2 = acc[nt][2], c3 = acc[nt][3];
        *(float2*)&stagef[(rw+qr)*132 + col]   = make_float2(c0, c1);
        *(float2*)&stagef[(rw+qr+8)*132 + col] = make_float2(c2, c3);
        float2 alv = *(const float2*)&al[col];
        float2 arv = *(const float2*)&ar[col];
        int h = nt >> 2;
        sl0[h] += c0*alv.x + c1*alv.y;  sr0[h] += c0*arv.x + c1*arv.y;
        sl1[h] += c2*alv.x + c3*alv.y;  sr1[h] += c2*arv.x + c3*arv.y;
    }
    #pragma unroll
    for (int h = 0; h < 4; h++){
        sl0[h] += __shfl_xor_sync(0xffffffffu, sl0[h], 1);
        sl0[h] += __shfl_xor_sync(0xffffffffu, sl0[h], 2);
        sr0[h] += __shfl_xor_sync(0xffffffffu, sr0[h], 1);
        sr0[h] += __shfl_xor_sync(0xffffffffu, sr0[h], 2);
        sl1[h] += __shfl_xor_sync(0xffffffffu, sl1[h], 1);
        sl1[h] += __shfl_xor_sync(0xffffffffu, sl1[h], 2);
        sr1[h] += __shfl_xor_sync(0xffffffffu, sr1[h], 1);
        sr1[h] += __shfl_xor_sync(0xffffffffu, sr1[h], 2);
    }
    if (qc == 0){
        int r0 = row0 + rw + qr;
        int r1 = r0 + 8;
        if (r0 < NN){
            #pragma unroll
            for (int h = 0; h < 4; h++){ g_el[r0*4+h] = sl0[h]; g_er[r0*4+h] = sr0[h]; }
        }
        if (r1 < NN){
            #pragma unroll
            for (int h = 0; h < 4; h++){ g_el[r1*4+h] = sl1[h]; g_er[r1*4+h] = sr1[h]; }
        }
    }
    __syncthreads();

    // ---- coalesced h writeback ----
    {
        float4* hd = (float4*)&g_h[(size_t)row0*DD];
        #pragma unroll 4
        for (int j = 0; j < 16; j++){
            int idx = j*256 + tid;
            int r = idx >> 5, c4 = idx & 31;
            hd[idx] = *(const float4*)&stagef[r*132 + c4*4];
        }
    }
}

// ---------------- fused edge-softmax + aggregation (warp per node) ---------
// self loop handled analytically. MODE: 0 = g_h gather (emits split-x),
// 1 = layer-0 rank-1 (emits split-x), 2 = g_h gather + prediction head
template<int MODE>
__device__ __forceinline__ void smax_aggr_body(
    const float* __restrict__ bias, const float* __restrict__ weights,
    const float* __restrict__ pw, const float* __restrict__ pb,
    float* __restrict__ out)
{
    int wid = (blockIdx.x*blockDim.x + threadIdx.x) >> 5;
    if (wid >= NN) return;
    int lane = threadIdx.x & 31;
    int wd   = (threadIdx.x >> 5) & 7;
    __shared__ float sAlpha[8][128];
    __shared__ int   sSrc[8][32];

    int start = wid * BKT;
    int deg   = g_deg[wid];                  // excludes self
    if (deg > BKT) deg = BKT;

    // ---- phase 1: e + max (lanes over (edge,head)) ----
    int eh_e = lane >> 2;                    // edge slot within chunk (0..7)
    int eh_h = lane & 3;                     // head
    float wself, er_h, e_self;
    if (MODE == 1){
        wself = weights[wid];
        er_h  = wself*g_cr[eh_h] + g_dr[eh_h];
        e_self = lrelu02(wself*g_cl[eh_h] + g_dl[eh_h] + er_h);
    } else {
        wself = 0.f;
        er_h  = g_er[wid*4 + eh_h];
        e_self = lrelu02(g_el[wid*4 + eh_h] + er_h);
    }
    float ev[4];
    float mx = e_self;
    #pragma unroll
    for (int c = 0; c < 4; c++){
        int pi = c*8 + eh_e;
        float e = -3.0e38f;
        if (pi < deg){
            int s = g_csrc[start + pi];
            if (eh_h == 0) sSrc[wd][pi] = s;
            float els = (MODE == 1) ? (weights[s]*g_cl[eh_h] + g_dl[eh_h])
                                    : g_el[s*4 + eh_h];
            e = lrelu02(els + er_h);
        }
        ev[c] = e;
        mx = fmaxf(mx, e);
    }
    for (int pi = 32 + eh_e; pi < deg; pi += 8){          // rare overflow
        int s = g_csrc[start + pi];
        float els = (MODE == 1) ? (weights[s]*g_cl[eh_h] + g_dl[eh_h])
                                : g_el[s*4 + eh_h];
        mx = fmaxf(mx, lrelu02(els + er_h));
    }
    mx = fmaxf(mx, __shfl_xor_sync(0xffffffffu, mx, 4));
    mx = fmaxf(mx, __shfl_xor_sync(0xffffffffu, mx, 8));
    mx = fmaxf(mx, __shfl_xor_sync(0xffffffffu, mx, 16));

    // ---- phase 2: exp + sum ----
    float sum = (eh_e == 0) ? __expf(e_self - mx) : 0.f;
    #pragma unroll
    for (int c = 0; c < 4; c++){
        int pi = c*8 + eh_e;
        float a = 0.f;
        if (pi < deg) a = __expf(ev[c] - mx);
        ev[c] = a;
        sum += a;
    }
    for (int pi = 32 + eh_e; pi < deg; pi += 8){          // rare overflow
        int s = g_csrc[start + pi];
        float els = (MODE == 1) ? (weights[s]*g_cl[eh_h] + g_dl[eh_h])
                                : g_el[s*4 + eh_h];
        sum += __expf(lrelu02(els + er_h) - mx);
    }
    sum += __shfl_xor_sync(0xffffffffu, sum, 4);
    sum += __shfl_xor_sync(0xffffffffu, sum, 8);
    sum += __shfl_xor_sync(0xffffffffu, sum, 16);
    float invs = 1.0f / sum;

    #pragma unroll
    for (int c = 0; c < 4; c++){
        int pi = c*8 + eh_e;
        if (pi < deg && pi < 32) sAlpha[wd][pi*4 + eh_h] = ev[c]*invs;
    }
    __syncwarp();

    // ---- phase 3: aggregate over features (4x unrolled for MLP) ----
    int head = lane >> 3;
    float invs_h   = __shfl_sync(0xffffffffu, invs,   head);
    float mx_h     = __shfl_sync(0xffffffffu, mx,     head);
    float er_hh    = __shfl_sync(0xffffffffu, er_h,   head);
    float e_self_h = __shfl_sync(0xffffffffu, e_self, head);

    float4 acc = *(const float4*)&bias[lane*4];
    float4 c4, d4;
    if (MODE == 1){
        c4 = *(const float4*)&g_c[lane*4];
        d4 = *(const float4*)&g_d[lane*4];
    }
    // self contribution
    {
        float a_self = __expf(e_self_h - mx_h) * invs_h;
        if (MODE == 1){
            acc.x += (wself*c4.x + d4.x)*a_self;
            acc.y += (wself*c4.y + d4.y)*a_self;
            acc.z += (wself*c4.z + d4.z)*a_self;
            acc.w += (wself*c4.w + d4.w)*a_self;
        } else {
            float4 hv = *(const float4*)&g_h[(size_t)wid*DD + lane*4];
            acc.x += hv.x*a_self; acc.y += hv.y*a_self;
            acc.z += hv.z*a_self; acc.w += hv.w*a_self;
        }
    }
    int lim = deg < 32 ? deg : 32;
    int p = 0;
    for (; p + 4 <= lim; p += 4){
        int s0 = sSrc[wd][p],   s1 = sSrc[wd][p+1];
        int s2 = sSrc[wd][p+2], s3 = sSrc[wd][p+3];
        float w0 = sAlpha[wd][p*4 + head],     w1 = sAlpha[wd][(p+1)*4 + head];
        float w2 = sAlpha[wd][(p+2)*4 + head], w3 = sAlpha[wd][(p+3)*4 + head];
        if (MODE == 1){
            float ws0 = weights[s0], ws1 = weights[s1];
            float ws2 = weights[s2], ws3 = weights[s3];
            float wsum = w0 + w1 + w2 + w3;
            float wws  = ws0*w0 + ws1*w1 + ws2*w2 + ws3*w3;
            acc.x += wws*c4.x + wsum*d4.x;
            acc.y += wws*c4.y + wsum*d4.y;
            acc.z += wws*c4.z + wsum*d4.z;
            acc.w += wws*c4.w + wsum*d4.w;
        } else {
            float4 h0 = *(const float4*)&g_h[(size_t)s0*DD + lane*4];
            float4 h1 = *(const float4*)&g_h[(size_t)s1*DD + lane*4];
            float4 h2 = *(const float4*)&g_h[(size_t)s2*DD + lane*4];
            float4 h3 = *(const float4*)&g_h[(size_t)s3*DD + lane*4];
            acc.x += h0.x*w0 + h1.x*w1 + h2.x*w2 + h3.x*w3;
            acc.y += h0.y*w0 + h1.y*w1 + h2.y*w2 + h3.y*w3;
            acc.z += h0.z*w0 + h1.z*w1 + h2.z*w2 + h3.z*w3;
            acc.w += h0.w*w0 + h1.w*w1 + h2.w*w2 + h3.w*w3;
        }
    }
    for (; p < lim; p++){
        int s   = sSrc[wd][p];
        float w = sAlpha[wd][p*4 + head];
        if (MODE == 1){
            float ws = weights[s];
            acc.x += (ws*c4.x + d4.x)*w;
            acc.y += (ws*c4.y + d4.y)*w;
            acc.z += (ws*c4.z + d4.z)*w;
            acc.w += (ws*c4.w + d4.w)*w;
        } else {
            float4 hv = *(const float4*)&g_h[(size_t)s*DD + lane*4];
            acc.x += hv.x*w; acc.y += hv.y*w; acc.z += hv.z*w; acc.w += hv.w*w;
        }
    }
    for (p = 32; p < deg; p++){                           // rare overflow
        int s = g_csrc[start + p];
        float els = (MODE == 1) ? (weights[s]*g_cl[head] + g_dl[head])
                                : g_el[s*4 + head];
        float w = __expf(lrelu02(els + er_hh) - mx_h) * invs_h;
        if (MODE == 1){
            float ws = weights[s];
            acc.x += (ws*c4.x + d4.x)*w;
            acc.y += (ws*c4.y + d4.y)*w;
            acc.z += (ws*c4.z + d4.z)*w;
            acc.w += (ws*c4.w + d4.w)*w;
        } else {
            float4 hv = *(const float4*)&g_h[(size_t)s*DD + lane*4];
            acc.x += hv.x*w; acc.y += hv.y*w; acc.z += hv.z*w; acc.w += hv.w*w;
        }
    }

    if (MODE == 2){
        float4 wv = *(const float4*)&pw[lane*4];
        float sdot = acc.x*wv.x + acc.y*wv.y + acc.z*wv.z + acc.w*wv.w;
        #pragma unroll
        for (int o = 16; o; o >>= 1) sdot += __shfl_down_sync(0xffffffffu, sdot, o);
        if (lane == 0) out[wid] = sdot + pb[0];
    } else {
        // emit leaky(x) pre-split to bf16 hi/lo for the next GEMM
        // row = 64 uint32 = 32 uint2; this lane owns uint2 slot `lane`
        float a0 = lrelu001(acc.x), a1 = lrelu001(acc.y);
        float a2 = lrelu001(acc.z), a3 = lrelu001(acc.w);
        uint32_t lo0, lo1;
        uint32_t hi0 = bfsplit2(a0, a1, lo0);
        uint32_t hi1 = bfsplit2(a2, a3, lo1);
        ((uint2*)g_xh)[(size_t)wid*32 + lane] = make_uint2(hi0, hi1);
        ((uint2*)g_xl)[(size_t)wid*32 + lane] = make_uint2(lo0, lo1);
    }
}

__global__ void k_smax_aggr(const float* __restrict__ bias){
    smax_aggr_body<0>(bias, nullptr, nullptr, nullptr, nullptr);
}
__global__ void k_smax_aggr0(const float* __restrict__ weights,
                             const float* __restrict__ bias){
    smax_aggr_body<1>(bias, weights, nullptr, nullptr, nullptr);
}
__global__ void k_smax_aggr_pred(const float* __restrict__ bias,
                                 const float* __restrict__ pw,
                                 const float* __restrict__ pb,
                                 float* __restrict__ out){
    smax_aggr_body<2>(bias, nullptr, pw, pb, out);
}

// ---------------- launch ----------------------------------------------------
// NOTE: never pass __device__ symbols as kernel arguments from host code —
// on GB300 (ATS) that silently binds the HOST shadow variable.
extern "C" void kernel_launch(void* const* d_in, const int* in_sizes, int n_in,
                              void* d_out, int out_size){
    const float* weights = (const float*)d_in[0];
    const float* lin_W   = (const float*)d_in[1];
    const float* lin_b   = (const float*)d_in[2];
    const float* fc_W    = (const float*)d_in[3];
    const float* attn_l  = (const float*)d_in[4];
    const float* attn_r  = (const float*)d_in[5];
    const float* conv_b  = (const float*)d_in[6];
    const float* pred_W  = (const float*)d_in[7];
    const float* pred_b  = (const float*)d_in[8];
    const int*   src     = (const int*)d_in[9];
    const int*   dst     = (const int*)d_in[10];
    float* out = (float*)d_out;

    static int smem_set = 0;
    if (!smem_set){
        cudaFuncSetAttribute(k_hgemm, cudaFuncAttributeMaxDynamicSharedMemorySize, SM_BYTES);
        smem_set = 1;
    }

    // --- bucket CSR build + layer-0 prep + W pre-conversion ---
    k_init<<<(NN+255)/256, 256>>>(lin_W, lin_b, fc_W, attn_l, attn_r);
    k_fillbucket<<<(EE+255)/256, 256>>>(src, dst);
    k_wconv<<<32, 256>>>(fc_W);

    // --- layer 0 (rank-1 features; el/er computed inline; emits split-x) ---
    k_smax_aggr0<<<(NN*32+255)/256, 256>>>(weights, conv_b);

    // --- layer 1 (HMMA GEMM fuses el/er epilogue) ---
    k_hgemm<<<NNP/128, 256, SM_BYTES>>>(0, attn_l + 1*DD, attn_r + 1*DD);
    k_smax_aggr<<<(NN*32+255)/256, 256>>>(conv_b + 1*DD);

    // --- layer 2 ---
    k_hgemm<<<NNP/128, 256, SM_BYTES>>>(1, attn_l + 2*DD, attn_r + 2*DD);
    k_smax_aggr_pred<<<(NN*32+255)/256, 256>>>(conv_b + 2*DD, pred_W, pred_b, out);
}

// round 14
// speedup vs baseline: 1.3801x; 1.3801x over previous
#include <cuda_runtime.h>
#include <cuda_bf16.h>
#include <cstdint>

#define NN   100000
#define NNP  100096          // 782 * 128 (row-padded for GEMM tiles)
#define EE   600000
#define DD   128
#define HH   4
#define FF   32
#define NB4  (NN*4)
#define BKT  64              // bucket slots per node (P(deg>64) ~ 1e-40)

typedef unsigned long long ull;

// ---------------- scratch: device symbols, used ONLY inside device code ----
__device__ __align__(256) float g_x[NNP*DD];   // current node features
__device__ __align__(256) float g_h[NNP*DD];   // fc output of current layer
__device__ __align__(256) float g_el[NB4];
__device__ __align__(256) float g_er[NB4];
__device__ __align__(256) int   g_deg[NN];     // WITHOUT self loop
__device__ __align__(256) int   g_csrc[NN*BKT];
__device__ __align__(256) float g_c[DD];
__device__ __align__(256) float g_d[DD];
__device__ float g_cl[HH], g_dl[HH], g_cr[HH], g_dr[HH];

__device__ __forceinline__ float lrelu02(float x){ return (x >= 0.f) ? x : 0.2f*x; }

// bf16 hi/lo split of two floats -> packed bf16x2 words
__device__ __forceinline__ uint32_t bfsplit2(float x0, float x1, uint32_t& lo){
    __nv_bfloat16 h0 = __float2bfloat16(x0);
    __nv_bfloat16 h1 = __float2bfloat16(x1);
    float r0 = x0 - __bfloat162float(h0);
    float r1 = x1 - __bfloat162float(h1);
    __nv_bfloat16 g0 = __float2bfloat16(r0);
    __nv_bfloat16 g1 = __float2bfloat16(r1);
    lo = (uint32_t)__bfloat16_as_ushort(g0) | ((uint32_t)__bfloat16_as_ushort(g1) << 16);
    return (uint32_t)__bfloat16_as_ushort(h0) | ((uint32_t)__bfloat16_as_ushort(h1) << 16);
}

// warp-level bf16 MMA (baseline sm_80+ PTX; compiles at compute_103)
#define MMA_BF16(d, a, b0, b1) \
    asm volatile("mma.sync.aligned.m16n8k16.row.col.f32.bf16.bf16.f32 " \
        "{%0,%1,%2,%3}, {%4,%5,%6,%7}, {%8,%9}, {%0,%1,%2,%3};" \
        : "+f"((d)[0]), "+f"((d)[1]), "+f"((d)[2]), "+f"((d)[3]) \
        : "r"((a)[0]), "r"((a)[1]), "r"((a)[2]), "r"((a)[3]), "r"(b0), "r"(b1))

// ---------------- init: zero deg + (block 0) layer-0 rank-1 prep ------------
__global__ void k_init(const float* __restrict__ linW, const float* __restrict__ linb,
                       const float* __restrict__ W0,
                       const float* __restrict__ al0, const float* __restrict__ ar0){
    int i = blockIdx.x*blockDim.x + threadIdx.x;
    if (i < NN) g_deg[i] = 0;
    if (blockIdx.x == 0 && threadIdx.x < 128){
        int j = threadIdx.x;
        float c = 0.f, d = 0.f;
        const float* wr = W0 + j*DD;
        #pragma unroll 8
        for (int k = 0; k < DD; k++){
            float w = wr[k];
            c += linW[k]*w;
            d += linb[k]*w;
        }
        g_c[j] = c; g_d[j] = d;
        float alv = al0[j], arv = ar0[j];
        float cl = c*alv, dl = d*alv, cr = c*arv, dr = d*arv;
        #pragma unroll
        for (int o = 16; o; o >>= 1){
            cl += __shfl_down_sync(0xffffffffu, cl, o);
            dl += __shfl_down_sync(0xffffffffu, dl, o);
            cr += __shfl_down_sync(0xffffffffu, cr, o);
            dr += __shfl_down_sync(0xffffffffu, dr, o);
        }
        int lane = j & 31, hd = j >> 5;
        if (lane == 0){ g_cl[hd]=cl; g_dl[hd]=dl; g_cr[hd]=cr; g_dr[hd]=dr; }
    }
}

// ---------------- bucket fill: hist + fill fused (no scan needed) -----------
__global__ void k_fillbucket(const int* __restrict__ src, const int* __restrict__ dst){
    int i = blockIdx.x*blockDim.x + threadIdx.x;
    if (i < EE){
        int d = dst[i];
        int pos = atomicAdd(&g_deg[d], 1);
        if (pos < BKT) g_csrc[d*BKT + pos] = src[i];
    }
}

// ---------------- HMMA split-bf16 GEMM + fused el/er (layers 1,2) ----------
// Each block: 128 rows x 64 cols (half of N) -> smem 104.4KB -> 2 CTAs/SM.
// h = Ahi*Whi + Ahi*Wlo + Alo*Whi (fp32 accum). Half covers exactly 2 heads.
#define WP 68
#define SM_BYTES (384*WP*4)     // Whi(64)+Wlo(64)+Xhi(128)+Xlo(128) rows * WP

__global__ void __launch_bounds__(256)
k_hgemm(const float* __restrict__ W,
        const float* __restrict__ al, const float* __restrict__ ar){
    extern __shared__ __align__(16) uint32_t sm[];
    uint32_t* Whi = sm;                    //  64*WP words
    uint32_t* Wlo = sm +  64*WP;
    uint32_t* Xhi = sm + 128*WP;           // 128*WP words
    uint32_t* Xlo = sm + 256*WP;
    float*    stagef = (float*)sm;         // reuse W region after MMA (post-sync)

    int tid  = threadIdx.x;
    int w    = tid >> 5;
    int lane = tid & 31;
    int qr   = lane >> 2, qc = lane & 3;
    int tile  = blockIdx.x >> 1;
    int nhalf = blockIdx.x & 1;
    int row0 = tile * 128;
    int col0 = nhalf * 64;
    int rw   = w * 16;

    // ---- convert W half (64 rows) + x tile (128 rows) to split-bf16 smem ----
    {
        const float4* ws = (const float4*)&W[(size_t)col0*DD];
        #pragma unroll
        for (int j = 0; j < 8; j++){
            int idx = j*256 + tid;                 // float4 index (2048 total)
            int r = idx >> 5, c4 = idx & 31;
            float4 v = ws[idx];
            uint32_t lo0, lo1;
            uint32_t hi0 = bfsplit2(v.x, v.y, lo0);
            uint32_t hi1 = bfsplit2(v.z, v.w, lo1);
            Whi[r*WP + c4*2]     = hi0; Whi[r*WP + c4*2 + 1] = hi1;
            Wlo[r*WP + c4*2]     = lo0; Wlo[r*WP + c4*2 + 1] = lo1;
        }
        const float4* xs = (const float4*)&g_x[(size_t)row0*DD];
        #pragma unroll 4
        for (int j = 0; j < 16; j++){
            int idx = j*256 + tid;                 // float4 index (4096 total)
            int r = idx >> 5, c4 = idx & 31;
            float4 u = xs[idx];
            u.x = (u.x >= 0.f) ? u.x : 0.01f*u.x;
            u.y = (u.y >= 0.f) ? u.y : 0.01f*u.y;
            u.z = (u.z >= 0.f) ? u.z : 0.01f*u.z;
            u.w = (u.w >= 0.f) ? u.w : 0.01f*u.w;
            uint32_t lo0, lo1;
            uint32_t xh0 = bfsplit2(u.x, u.y, lo0);
            uint32_t xh1 = bfsplit2(u.z, u.w, lo1);
            Xhi[r*WP + c4*2]     = xh0; Xhi[r*WP + c4*2 + 1] = xh1;
            Xlo[r*WP + c4*2]     = lo0; Xlo[r*WP + c4*2 + 1] = lo1;
        }
    }
    __syncthreads();

    // ---- compute: warp w owns rows rw..rw+15, 64 cols of this half ----
    float acc[8][4];
    #pragma unroll
    for (int nt = 0; nt < 8; nt++)
        #pragma unroll
        for (int i = 0; i < 4; i++) acc[nt][i] = 0.f;

    #pragma unroll
    for (int ks = 0; ks < 8; ks++){
        int abase = (rw + qr)*WP + ks*8 + qc;
        uint32_t ahi[4], alo[4];
        ahi[0] = Xhi[abase];          ahi[1] = Xhi[abase + 8*WP];
        ahi[2] = Xhi[abase + 4];      ahi[3] = Xhi[abase + 8*WP + 4];
        alo[0] = Xlo[abase];          alo[1] = Xlo[abase + 8*WP];
        alo[2] = Xlo[abase + 4];      alo[3] = Xlo[abase + 8*WP + 4];
        #pragma unroll
        for (int nt = 0; nt < 8; nt++){
            int bbase = (nt*8 + qr)*WP + ks*8 + qc;
            uint32_t bh0 = Whi[bbase], bh1 = Whi[bbase + 4];
            uint32_t bl0 = Wlo[bbase], bl1 = Wlo[bbase + 4];
            MMA_BF16(acc[nt], ahi, bh0, bh1);
            MMA_BF16(acc[nt], ahi, bl0, bl1);
            MMA_BF16(acc[nt], alo, bh0, bh1);
        }
    }
    __syncthreads();                              // all warps done reading smem

    // ---- epilogue: stage h half + el/er (2 heads) from fragments ----
    float sl0[2], sr0[2], sl1[2], sr1[2];
    #pragma unroll
    for (int h = 0; h < 2; h++){ sl0[h]=0.f; sr0[h]=0.f; sl1[h]=0.f; sr1[h]=0.f; }
    #pragma unroll
    for (int nt = 0; nt < 8; nt++){
        int lcol = nt*8 + qc*2;
        float c0 = acc[nt][0], c1 = acc[nt][1], c2 = acc[nt][2], c3 = acc[nt][3];
        *(float2*)&stagef[(rw+qr)*68 + lcol]   = make_float2(c0, c1);
        *(float2*)&stagef[(rw+qr+8)*68 + lcol] = make_float2(c2, c3);
        float2 alv = *(const float2*)&al[col0 + lcol];
        float2 arv = *(const float2*)&ar[col0 + lcol];
        int hh = nt >> 2;
        sl0[hh] += c0*alv.x + c1*alv.y;  sr0[hh] += c0*arv.x + c1*arv.y;
        sl1[hh] += c2*alv.x + c3*alv.y;  sr1[hh] += c2*arv.x + c3*arv.y;
    }
    #pragma unroll
    for (int h = 0; h < 2; h++){
        sl0[h] += __shfl_xor_sync(0xffffffffu, sl0[h], 1);
        sl0[h] += __shfl_xor_sync(0xffffffffu, sl0[h], 2);
        sr0[h] += __shfl_xor_sync(0xffffffffu, sr0[h], 1);
        sr0[h] += __shfl_xor_sync(0xffffffffu, sr0[h], 2);
        sl1[h] += __shfl_xor_sync(0xffffffffu, sl1[h], 1);
        sl1[h] += __shfl_xor_sync(0xffffffffu, sl1[h], 2);
        sr1[h] += __shfl_xor_sync(0xffffffffu, sr1[h], 1);
        sr1[h] += __shfl_xor_sync(0xffffffffu, sr1[h], 2);
    }
    if (qc == 0){
        int r0 = row0 + rw + qr;
        int r1 = r0 + 8;
        int hb = nhalf*2;
        if (r0 < NN){
            #pragma unroll
            for (int h = 0; h < 2; h++){ g_el[r0*4+hb+h] = sl0[h]; g_er[r0*4+hb+h] = sr0[h]; }
        }
        if (r1 < NN){
            #pragma unroll
            for (int h = 0; h < 2; h++){ g_el[r1*4+hb+h] = sl1[h]; g_er[r1*4+hb+h] = sr1[h]; }
        }
    }
    __syncthreads();

    // ---- coalesced h writeback (this half's 64 cols) ----
    {
        float4* hd = (float4*)&g_h[(size_t)row0*DD];
        #pragma unroll
        for (int j = 0; j < 8; j++){
            int idx = j*256 + tid;                // float4 index (2048 total)
            int r = idx >> 4, c4 = idx & 15;
            hd[r*32 + nhalf*16 + c4] = *(const float4*)&stagef[r*68 + c4*4];
        }
    }
}

// ---------------- fused edge-softmax + aggregation (warp per node) ---------
// self loop handled analytically (not in bucket). MODE: 0 = g_h gather,
// 1 = layer-0 rank-1 (el/er from weights inline), 2 = g_h + prediction head
template<int MODE>
__device__ __forceinline__ void smax_aggr_body(
    const float* __restrict__ bias, const float* __restrict__ weights,
    const float* __restrict__ pw, const float* __restrict__ pb,
    float* __restrict__ out)
{
    int wid = (blockIdx.x*blockDim.x + threadIdx.x) >> 5;
    if (wid >= NN) return;
    int lane = threadIdx.x & 31;
    int wd   = (threadIdx.x >> 5) & 7;
    __shared__ float sAlpha[8][128];
    __shared__ int   sSrc[8][32];

    int start = wid * BKT;
    int deg   = g_deg[wid];                  // excludes self
    if (deg > BKT) deg = BKT;

    // ---- phase 1: e + max (lanes over (edge,head)) ----
    int eh_e = lane >> 2;                    // edge slot within chunk (0..7)
    int eh_h = lane & 3;                     // head
    float wself, er_h, e_self;
    if (MODE == 1){
        wself = weights[wid];
        er_h  = wself*g_cr[eh_h] + g_dr[eh_h];
        e_self = lrelu02(wself*g_cl[eh_h] + g_dl[eh_h] + er_h);
    } else {
        wself = 0.f;
        er_h  = g_er[wid*4 + eh_h];
        e_self = lrelu02(g_el[wid*4 + eh_h] + er_h);
    }
    float ev[4];
    float mx = e_self;
    #pragma unroll
    for (int c = 0; c < 4; c++){
        int pi = c*8 + eh_e;
        float e = -3.0e38f;
        if (pi < deg){
            int s = g_csrc[start + pi];
            if (eh_h == 0) sSrc[wd][pi] = s;
            float els = (MODE == 1) ? (weights[s]*g_cl[eh_h] + g_dl[eh_h])
                                    : g_el[s*4 + eh_h];
            e = lrelu02(els + er_h);
        }
        ev[c] = e;
        mx = fmaxf(mx, e);
    }
    for (int pi = 32 + eh_e; pi < deg; pi += 8){          // rare overflow
        int s = g_csrc[start + pi];
        float els = (MODE == 1) ? (weights[s]*g_cl[eh_h] + g_dl[eh_h])
                                : g_el[s*4 + eh_h];
        mx = fmaxf(mx, lrelu02(els + er_h));
    }
    mx = fmaxf(mx, __shfl_xor_sync(0xffffffffu, mx, 4));
    mx = fmaxf(mx, __shfl_xor_sync(0xffffffffu, mx, 8));
    mx = fmaxf(mx, __shfl_xor_sync(0xffffffffu, mx, 16));

    // ---- phase 2: exp + sum ----
    float sum = (eh_e == 0) ? __expf(e_self - mx) : 0.f;
    #pragma unroll
    for (int c = 0; c < 4; c++){
        int pi = c*8 + eh_e;
        float a = 0.f;
        if (pi < deg) a = __expf(ev[c] - mx);
        ev[c] = a;
        sum += a;
    }
    for (int pi = 32 + eh_e; pi < deg; pi += 8){          // rare overflow
        int s = g_csrc[start + pi];
        float els = (MODE == 1) ? (weights[s]*g_cl[eh_h] + g_dl[eh_h])
                                : g_el[s*4 + eh_h];
        sum += __expf(lrelu02(els + er_h) - mx);
    }
    sum += __shfl_xor_sync(0xffffffffu, sum, 4);
    sum += __shfl_xor_sync(0xffffffffu, sum, 8);
    sum += __shfl_xor_sync(0xffffffffu, sum, 16);
    float invs = 1.0f / sum;

    #pragma unroll
    for (int c = 0; c < 4; c++){
        int pi = c*8 + eh_e;
        if (pi < deg && pi < 32) sAlpha[wd][pi*4 + eh_h] = ev[c]*invs;
    }
    __syncwarp();

    // ---- phase 3: aggregate over features (4x unrolled for MLP) ----
    int head = lane >> 3;
    float invs_h   = __shfl_sync(0xffffffffu, invs,   head);
    float mx_h     = __shfl_sync(0xffffffffu, mx,     head);
    float er_hh    = __shfl_sync(0xffffffffu, er_h,   head);
    float e_self_h = __shfl_sync(0xffffffffu, e_self, head);

    float4 acc = *(const float4*)&bias[lane*4];
    float4 c4, d4;
    if (MODE == 1){
        c4 = *(const float4*)&g_c[lane*4];
        d4 = *(const float4*)&g_d[lane*4];
    }
    // self contribution
    {
        float a_self = __expf(e_self_h - mx_h) * invs_h;
        if (MODE == 1){
            acc.x += (wself*c4.x + d4.x)*a_self;
            acc.y += (wself*c4.y + d4.y)*a_self;
            acc.z += (wself*c4.z + d4.z)*a_self;
            acc.w += (wself*c4.w + d4.w)*a_self;
        } else {
            float4 hv = *(const float4*)&g_h[(size_t)wid*DD + lane*4];
            acc.x += hv.x*a_self; acc.y += hv.y*a_self;
            acc.z += hv.z*a_self; acc.w += hv.w*a_self;
        }
    }
    int lim = deg < 32 ? deg : 32;
    int p = 0;
    for (; p + 4 <= lim; p += 4){
        int s0 = sSrc[wd][p],   s1 = sSrc[wd][p+1];
        int s2 = sSrc[wd][p+2], s3 = sSrc[wd][p+3];
        float w0 = sAlpha[wd][p*4 + head],     w1 = sAlpha[wd][(p+1)*4 + head];
        float w2 = sAlpha[wd][(p+2)*4 + head], w3 = sAlpha[wd][(p+3)*4 + head];
        if (MODE == 1){
            float ws0 = weights[s0], ws1 = weights[s1];
            float ws2 = weights[s2], ws3 = weights[s3];
            float wsum = w0 + w1 + w2 + w3;
            float wws  = ws0*w0 + ws1*w1 + ws2*w2 + ws3*w3;
            acc.x += wws*c4.x + wsum*d4.x;
            acc.y += wws*c4.y + wsum*d4.y;
            acc.z += wws*c4.z + wsum*d4.z;
            acc.w += wws*c4.w + wsum*d4.w;
        } else {
            float4 h0 = *(const float4*)&g_h[(size_t)s0*DD + lane*4];
            float4 h1 = *(const float4*)&g_h[(size_t)s1*DD + lane*4];
            float4 h2 = *(const float4*)&g_h[(size_t)s2*DD + lane*4];
            float4 h3 = *(const float4*)&g_h[(size_t)s3*DD + lane*4];
            acc.x += h0.x*w0 + h1.x*w1 + h2.x*w2 + h3.x*w3;
            acc.y += h0.y*w0 + h1.y*w1 + h2.y*w2 + h3.y*w3;
            acc.z += h0.z*w0 + h1.z*w1 + h2.z*w2 + h3.z*w3;
            acc.w += h0.w*w0 + h1.w*w1 + h2.w*w2 + h3.w*w3;
        }
    }
    for (; p < lim; p++){
        int s   = sSrc[wd][p];
        float w = sAlpha[wd][p*4 + head];
        if (MODE == 1){
            float ws = weights[s];
            acc.x += (ws*c4.x + d4.x)*w;
            acc.y += (ws*c4.y + d4.y)*w;
            acc.z += (ws*c4.z + d4.z)*w;
            acc.w += (ws*c4.w + d4.w)*w;
        } else {
            float4 hv = *(const float4*)&g_h[(size_t)s*DD + lane*4];
            acc.x += hv.x*w; acc.y += hv.y*w; acc.z += hv.z*w; acc.w += hv.w*w;
        }
    }
    for (p = 32; p < deg; p++){                           // rare overflow
        int s = g_csrc[start + p];
        float els = (MODE == 1) ? (weights[s]*g_cl[head] + g_dl[head])
                                : g_el[s*4 + head];
        float w = __expf(lrelu02(els + er_hh) - mx_h) * invs_h;
        if (MODE == 1){
            float ws = weights[s];
            acc.x += (ws*c4.x + d4.x)*w;
            acc.y += (ws*c4.y + d4.y)*w;
            acc.z += (ws*c4.z + d4.z)*w;
            acc.w += (ws*c4.w + d4.w)*w;
        } else {
            float4 hv = *(const float4*)&g_h[(size_t)s*DD + lane*4];
            acc.x += hv.x*w; acc.y += hv.y*w; acc.z += hv.z*w; acc.w += hv.w*w;
        }
    }

    if (MODE == 2){
        float4 wv = *(const float4*)&pw[lane*4];
        float sdot = acc.x*wv.x + acc.y*wv.y + acc.z*wv.z + acc.w*wv.w;
        #pragma unroll
        for (int o = 16; o; o >>= 1) sdot += __shfl_down_sync(0xffffffffu, sdot, o);
        if (lane == 0) out[wid] = sdot + pb[0];
    } else {
        *(float4*)&g_x[(size_t)wid*DD + lane*4] = acc;
    }
}

__global__ void k_smax_aggr(const float* __restrict__ bias){
    smax_aggr_body<0>(bias, nullptr, nullptr, nullptr, nullptr);
}
__global__ void k_smax_aggr0(const float* __restrict__ weights,
                             const float* __restrict__ bias){
    smax_aggr_body<1>(bias, weights, nullptr, nullptr, nullptr);
}
__global__ void k_smax_aggr_pred(const float* __restrict__ bias,
                                 const float* __restrict__ pw,
                                 const float* __restrict__ pb,
                                 float* __restrict__ out){
    smax_aggr_body<2>(bias, nullptr, pw, pb, out);
}

// ---------------- launch ----------------------------------------------------
// NOTE: never pass __device__ symbols as kernel arguments from host code —
// on GB300 (ATS) that silently binds the HOST shadow variable.
extern "C" void kernel_launch(void* const* d_in, const int* in_sizes, int n_in,
                              void* d_out, int out_size){
    const float* weights = (const float*)d_in[0];
    const float* lin_W   = (const float*)d_in[1];
    const float* lin_b   = (const float*)d_in[2];
    const float* fc_W    = (const float*)d_in[3];
    const float* attn_l  = (const float*)d_in[4];
    const float* attn_r  = (const float*)d_in[5];
    const float* conv_b  = (const float*)d_in[6];
    const float* pred_W  = (const float*)d_in[7];
    const float* pred_b  = (const float*)d_in[8];
    const int*   src     = (const int*)d_in[9];
    const int*   dst     = (const int*)d_in[10];
    float* out = (float*)d_out;

    static int smem_set = 0;
    if (!smem_set){
        cudaFuncSetAttribute(k_hgemm, cudaFuncAttributeMaxDynamicSharedMemorySize, SM_BYTES);
        smem_set = 1;
    }

    // --- bucket CSR build (no scans) + layer-0 prep fused into k_init ---
    k_init<<<(NN+255)/256, 256>>>(lin_W, lin_b, fc_W, attn_l, attn_r);
    k_fillbucket<<<(EE+255)/256, 256>>>(src, dst);

    // --- layer 0 (rank-1 features; el/er computed inline) ---
    k_smax_aggr0<<<(NN*32+255)/256, 256>>>(weights, conv_b);

    // --- layer 1 (HMMA GEMM fuses el/er epilogue; 2 blocks per row-tile) ---
    k_hgemm<<<2*(NNP/128), 256, SM_BYTES>>>(fc_W + 1*DD*DD, attn_l + 1*DD, attn_r + 1*DD);
    k_smax_aggr<<<(NN*32+255)/256, 256>>>(conv_b + 1*DD);

    // --- layer 2 ---
    k_hgemm<<<2*(NNP/128), 256, SM_BYTES>>>(fc_W + 2*DD*DD, attn_l + 2*DD, attn_r + 2*DD);
    k_smax_aggr_pred<<<(NN*32+255)/256, 256>>>(conv_b + 2*DD, pred_W, pred_b, out);
}